// round 9
// baseline (speedup 1.0000x reference)
#include <cuda_runtime.h>
#include <cstdint>

#define NN 100000
#define EE 1600000
#define FF 128
#define HH 4
#define LRELU_ALPHA 0.2f
#define CAP 64   // slots per node; degree ~ 1+Poisson(15), P(>64) ~ 1e-22

#define FULLM 0xFFFFFFFFu

// packed f32x2 fma: d = a*b + c lanewise on two packed fp32
#define FMA_F32X2(d, a, b, c) \
    asm("fma.rn.f32x2 %0, %1, %2, %3;" : "=l"(d) : "l"(a), "l"(b), "l"(c))
#define PACK_DUP(out, s) \
    asm("mov.b64 %0, {%1, %1};" : "=l"(out) : "f"(s))
#define UNPACK2(lo, hi, in) \
    asm("mov.b64 {%0, %1}, %2;" : "=f"(lo), "=f"(hi) : "l"(in))

struct __align__(32) Slot {
    float4 coef;   // 4-head edge coefficient
    int    dst;
    int    pad[3];
};

// ---- device scratch (no allocations allowed) ----
__device__ float4 g_ssrc[NN];               // per-node src-scores, 4 heads
__device__ float4 g_sdst[NN];               // per-node dst-scores, 4 heads
__device__ int    g_cnt[NN];                // per-node slot cursor / degree
__device__ Slot   g_slot[(size_t)NN * CAP]; // padded per-src edge bins

// K1: per-node scores, warp per node, float4 lanes, 9-shuffle reduction.
// Also zeroes g_cnt.
__global__ void k_scores(const float* __restrict__ x,
                         const float* __restrict__ W,
                         const float* __restrict__ a, int n) {
    // wa4[v][q]: v=0..3 -> s-part head v; v=4..7 -> d-part head v-4.
    // q indexes float4 feature quads (features q*4..q*4+3).
    __shared__ float4 wa4[8][32];
    int tid = threadIdx.x;
    for (int i = tid; i < 8 * 32; i += blockDim.x) {
        int v = i >> 5, q = i & 31;
        int h = v & 3;
        const float* wp = W + h * FF + q * 4;
        const float* ap = a + h * 2 * FF + ((v >= 4) ? FF : 0) + q * 4;
        wa4[v][q] = make_float4(wp[0] * ap[0], wp[1] * ap[1],
                                wp[2] * ap[2], wp[3] * ap[3]);
    }
    __syncthreads();
    int lane = tid & 31, warp = tid >> 5;
    int node = blockIdx.x * (blockDim.x >> 5) + warp;
    if (node >= n) return;
    if (lane == 16) g_cnt[node] = 0;

    float4 xv = ((const float4*)(x + (size_t)node * FF))[lane];
    float p[8];
#pragma unroll
    for (int v = 0; v < 8; v++) {
        float4 w4 = wa4[v][lane];
        p[v] = xv.x * w4.x + xv.y * w4.y + xv.z * w4.z + xv.w * w4.w;
    }
    // multi-value halving reduction: 8 values -> 1 per lane over lanes 0..7 orbit
#pragma unroll
    for (int s = 0; s < 3; s++) {
        int off = 1 << s;
        int half = 4 >> s;           // values exchanged this step
        bool hi = (lane >> s) & 1;
#pragma unroll
        for (int i = 0; i < 4; i++) {
            if (i < half) {
                float keep = hi ? p[i + half] : p[i];
                float send = hi ? p[i] : p[i + half];
                float recv = __shfl_xor_sync(FULLM, send, off);
                p[i] = keep + recv;
            }
        }
    }
    float tot = p[0];
    tot += __shfl_xor_sync(FULLM, tot, 8);
    tot += __shfl_xor_sync(FULLM, tot, 16);
    if (lane < 8) {
        int v = ((lane & 1) << 2) | (lane & 2) | ((lane >> 2) & 1);  // bitrev3
        float* dst = (v < 4) ? ((float*)&g_ssrc[node]) + v
                             : ((float*)&g_sdst[node]) + (v - 4);
        *dst = tot;
    }
}

// K2: per edge: 4-head coefficient -> slot bin of src (atomic cursor)
__global__ void k_fill(const int* __restrict__ src, const int* __restrict__ dst,
                       const float* __restrict__ adj, int e) {
    int i = blockIdx.x * blockDim.x + threadIdx.x;
    if (i >= e) return;
    int s = src[i], d = dst[i];
    float av = adj[i];
    float4 a4 = g_ssrc[s];
    float4 b4 = g_sdst[d];
    float z0 = a4.x + b4.x, z1 = a4.y + b4.y, z2 = a4.z + b4.z, z3 = a4.w + b4.w;
    z0 = z0 > 0.f ? z0 : LRELU_ALPHA * z0;
    z1 = z1 > 0.f ? z1 : LRELU_ALPHA * z1;
    z2 = z2 > 0.f ? z2 : LRELU_ALPHA * z2;
    z3 = z3 > 0.f ? z3 : LRELU_ALPHA * z3;
    float4 ec = make_float4(__expf(z0) * av, __expf(z1) * av,
                            __expf(z2) * av, __expf(z3) * av);
    int idx = atomicAdd(&g_cnt[s], 1);
    size_t o = (size_t)s * CAP + idx;
    g_slot[o].coef = ec;
    g_slot[o].dst  = d;
}

// K3: warp per output node. Lanes bulk-load slots, broadcast via shfl,
// accumulate with packed f32x2 FFMA (8 instead of 16 FFMA per edge).
__global__ void k_agg(const float* __restrict__ x, const float* __restrict__ W,
                      float* __restrict__ out, int n) {
    int lane = threadIdx.x & 31, warp = threadIdx.x >> 5;
    int node = blockIdx.x * (blockDim.x >> 5) + warp;
    if (node >= n) return;
    int cnt = g_cnt[node];
    size_t base = (size_t)node * CAP;

    unsigned long long acc01[HH], acc23[HH];
#pragma unroll
    for (int k = 0; k < HH; k++) { acc01[k] = 0ULL; acc23[k] = 0ULL; }
    float rs[HH] = {0.f, 0.f, 0.f, 0.f};

    for (int b = 0; b < cnt; b += 32) {
        int m = cnt - b; if (m > 32) m = 32;
        float4 myc = make_float4(0.f, 0.f, 0.f, 0.f);
        int myd = 0;
        if (lane < m) {
            const Slot& sl = g_slot[base + b + lane];
            myc = sl.coef;
            myd = sl.dst;
        }
        // rowsum: butterfly reduce of preloaded coefs
        float r0 = myc.x, r1 = myc.y, r2 = myc.z, r3 = myc.w;
#pragma unroll
        for (int o = 16; o > 0; o >>= 1) {
            r0 += __shfl_xor_sync(FULLM, r0, o);
            r1 += __shfl_xor_sync(FULLM, r1, o);
            r2 += __shfl_xor_sync(FULLM, r2, o);
            r3 += __shfl_xor_sync(FULLM, r3, o);
        }
        rs[0] += r0; rs[1] += r1; rs[2] += r2; rs[3] += r3;

        for (int j = 0; j < m; j++) {
            int d  = __shfl_sync(FULLM, myd, j);
            float c0 = __shfl_sync(FULLM, myc.x, j);
            float c1 = __shfl_sync(FULLM, myc.y, j);
            float c2 = __shfl_sync(FULLM, myc.z, j);
            float c3 = __shfl_sync(FULLM, myc.w, j);
            // x row as two packed f32x2 (8B lanes, already packed in memory)
            ulonglong2 xv2 = ((const ulonglong2*)(x + (size_t)d * FF))[lane];
            unsigned long long c2p;
            PACK_DUP(c2p, c0);
            FMA_F32X2(acc01[0], c2p, xv2.x, acc01[0]);
            FMA_F32X2(acc23[0], c2p, xv2.y, acc23[0]);
            PACK_DUP(c2p, c1);
            FMA_F32X2(acc01[1], c2p, xv2.x, acc01[1]);
            FMA_F32X2(acc23[1], c2p, xv2.y, acc23[1]);
            PACK_DUP(c2p, c2);
            FMA_F32X2(acc01[2], c2p, xv2.x, acc01[2]);
            FMA_F32X2(acc23[2], c2p, xv2.y, acc23[2]);
            PACK_DUP(c2p, c3);
            FMA_F32X2(acc01[3], c2p, xv2.x, acc01[3]);
            FMA_F32X2(acc23[3], c2p, xv2.y, acc23[3]);
        }
    }

    float inv[HH];
#pragma unroll
    for (int k = 0; k < HH; k++) inv[k] = 1.f / rs[k];
    float o[4] = {0.f, 0.f, 0.f, 0.f};
#pragma unroll
    for (int k = 0; k < HH; k++) {
        float a0, a1, a2, a3;
        UNPACK2(a0, a1, acc01[k]);
        UNPACK2(a2, a3, acc23[k]);
        float4 w4 = ((const float4*)(W + k * FF))[lane];
        float v0 = a0 * w4.x * inv[k];
        float v1 = a1 * w4.y * inv[k];
        float v2 = a2 * w4.z * inv[k];
        float v3 = a3 * w4.w * inv[k];
        o[0] += v0 > 0.f ? v0 : expm1f(v0);
        o[1] += v1 > 0.f ? v1 : expm1f(v1);
        o[2] += v2 > 0.f ? v2 : expm1f(v2);
        o[3] += v3 > 0.f ? v3 : expm1f(v3);
    }
    float4 res = make_float4(o[0] * 0.25f, o[1] * 0.25f, o[2] * 0.25f, o[3] * 0.25f);
    ((float4*)(out + (size_t)node * FF))[lane] = res;
}

extern "C" void kernel_launch(void* const* d_in, const int* in_sizes, int n_in,
                              void* d_out, int out_size) {
    const float* x   = (const float*)d_in[0];   // [N, F]
    const int*   edge = (const int*)d_in[1];    // [2, E]
    const float* adj = (const float*)d_in[2];   // [E]
    const float* W   = (const float*)d_in[3];   // [H, F]
    const float* a   = (const float*)d_in[4];   // [H, 2F]
    float* out = (float*)d_out;

    int n = in_sizes[0] / FF;
    int e = in_sizes[2];
    const int* src = edge;
    const int* dst = edge + e;

    k_scores<<<(n + 3) / 4, 128>>>(x, W, a, n);
    k_fill<<<(e + 255) / 256, 256>>>(src, dst, adj, e);
    k_agg<<<(n + 3) / 4, 128>>>(x, W, out, n);
}

// round 12
// speedup vs baseline: 1.2693x; 1.2693x over previous
#include <cuda_runtime.h>
#include <cstdint>

#define NN 100000
#define EE 1600000
#define FF 128
#define HH 4
#define LRELU_ALPHA 0.2f
#define CAP 64   // slots per node; degree ~ 1+Poisson(15), P(>64) ~ 1e-22

#define FULLM 0xFFFFFFFFu

struct __align__(32) Slot {
    float4 coef;   // 4-head edge coefficient
    int    dst;
    int    pad[3];
};

// ---- device scratch (no allocations allowed) ----
__device__ float4 g_ssrc[NN];               // per-node src-scores, 4 heads
__device__ float4 g_sdst[NN];               // per-node dst-scores, 4 heads
__device__ int    g_cnt[NN];                // per-node slot cursor / degree
__device__ Slot   g_slot[(size_t)NN * CAP]; // padded per-src edge bins

// K1: grid-stride warp-per-node scores; weights register-cached per lane.
// Also zeroes g_cnt.
__global__ void k_scores(const float* __restrict__ x,
                         const float* __restrict__ W,
                         const float* __restrict__ a, int n) {
    int lane = threadIdx.x & 31;
    int gwarp = (blockIdx.x * blockDim.x + threadIdx.x) >> 5;
    int nwarps = (gridDim.x * blockDim.x) >> 5;

    // Per-lane weight cache: v=0..3 s-part head v, v=4..7 d-part head v-4.
    // Lane owns feature quad [lane*4, lane*4+4).
    float4 wa[8];
#pragma unroll
    for (int v = 0; v < 8; v++) {
        int h = v & 3;
        float4 w4 = ((const float4*)(W + h * FF))[lane];
        float4 a4 = ((const float4*)(a + h * 2 * FF + ((v >= 4) ? FF : 0)))[lane];
        wa[v] = make_float4(w4.x * a4.x, w4.y * a4.y, w4.z * a4.z, w4.w * a4.w);
    }

    for (int node = gwarp; node < n; node += nwarps) {
        if (lane == 16) g_cnt[node] = 0;
        float4 xv = ((const float4*)(x + (size_t)node * FF))[lane];
        float p[8];
#pragma unroll
        for (int v = 0; v < 8; v++) {
            p[v] = xv.x * wa[v].x + xv.y * wa[v].y + xv.z * wa[v].z + xv.w * wa[v].w;
        }
        // multi-value halving reduction (proven in R8): 8 values -> lanes 0..7
#pragma unroll
        for (int s = 0; s < 3; s++) {
            int off = 1 << s;
            int half = 4 >> s;
            bool hi = (lane >> s) & 1;
#pragma unroll
            for (int i = 0; i < 4; i++) {
                if (i < half) {
                    float keep = hi ? p[i + half] : p[i];
                    float send = hi ? p[i] : p[i + half];
                    float recv = __shfl_xor_sync(FULLM, send, off);
                    p[i] = keep + recv;
                }
            }
        }
        float tot = p[0];
        tot += __shfl_xor_sync(FULLM, tot, 8);
        tot += __shfl_xor_sync(FULLM, tot, 16);
        if (lane < 8) {
            int v = ((lane & 1) << 2) | (lane & 2) | ((lane >> 2) & 1);  // bitrev3
            float* dst = (v < 4) ? ((float*)&g_ssrc[node]) + v
                                 : ((float*)&g_sdst[node]) + (v - 4);
            *dst = tot;
        }
    }
}

// K2: per edge: 4-head coefficient -> slot bin of src (atomic cursor)
__global__ void k_fill(const int* __restrict__ src, const int* __restrict__ dst,
                       const float* __restrict__ adj, int e) {
    int i = blockIdx.x * blockDim.x + threadIdx.x;
    if (i >= e) return;
    int s = src[i], d = dst[i];
    float av = adj[i];
    float4 a4 = g_ssrc[s];
    float4 b4 = g_sdst[d];
    float z0 = a4.x + b4.x, z1 = a4.y + b4.y, z2 = a4.z + b4.z, z3 = a4.w + b4.w;
    z0 = z0 > 0.f ? z0 : LRELU_ALPHA * z0;
    z1 = z1 > 0.f ? z1 : LRELU_ALPHA * z1;
    z2 = z2 > 0.f ? z2 : LRELU_ALPHA * z2;
    z3 = z3 > 0.f ? z3 : LRELU_ALPHA * z3;
    float4 ec = make_float4(__expf(z0) * av, __expf(z1) * av,
                            __expf(z2) * av, __expf(z3) * av);
    int idx = atomicAdd(&g_cnt[s], 1);
    size_t o = (size_t)s * CAP + idx;
    g_slot[o].coef = ec;
    g_slot[o].dst  = d;
}

// K3: warp per output node. Lanes bulk-load slots (coalesced) and stage them
// in smem; inner loop reads uniform smem (broadcast) + plain FFMA.
__global__ void k_agg(const float* __restrict__ x, const float* __restrict__ W,
                      float* __restrict__ out, int n) {
    __shared__ float4 s_coef[4][32];
    __shared__ int    s_dst[4][32];
    int lane = threadIdx.x & 31, warp = threadIdx.x >> 5;
    int node = blockIdx.x * (blockDim.x >> 5) + warp;
    if (node >= n) return;
    int cnt = g_cnt[node];
    size_t base = (size_t)node * CAP;

    float acc[HH][4];
#pragma unroll
    for (int k = 0; k < HH; k++)
#pragma unroll
        for (int c = 0; c < 4; c++) acc[k][c] = 0.f;
    float rs[HH] = {0.f, 0.f, 0.f, 0.f};

    for (int b = 0; b < cnt; b += 32) {
        int m = cnt - b; if (m > 32) m = 32;
        float4 myc = make_float4(0.f, 0.f, 0.f, 0.f);
        int myd = 0;
        if (lane < m) {
            const Slot& sl = g_slot[base + b + lane];
            myc = sl.coef;
            myd = sl.dst;
        }
        // rowsum: butterfly reduce of preloaded coefs
        float r0 = myc.x, r1 = myc.y, r2 = myc.z, r3 = myc.w;
#pragma unroll
        for (int o = 16; o > 0; o >>= 1) {
            r0 += __shfl_xor_sync(FULLM, r0, o);
            r1 += __shfl_xor_sync(FULLM, r1, o);
            r2 += __shfl_xor_sync(FULLM, r2, o);
            r3 += __shfl_xor_sync(FULLM, r3, o);
        }
        rs[0] += r0; rs[1] += r1; rs[2] += r2; rs[3] += r3;

        // stage chunk in smem for broadcast reads
        s_coef[warp][lane] = myc;
        s_dst[warp][lane]  = myd;
        __syncwarp();

        for (int j = 0; j < m; j++) {
            float4 cf = s_coef[warp][j];
            int d = s_dst[warp][j];
            float4 xv = ((const float4*)(x + (size_t)d * FF))[lane];
            acc[0][0] = fmaf(cf.x, xv.x, acc[0][0]);
            acc[0][1] = fmaf(cf.x, xv.y, acc[0][1]);
            acc[0][2] = fmaf(cf.x, xv.z, acc[0][2]);
            acc[0][3] = fmaf(cf.x, xv.w, acc[0][3]);
            acc[1][0] = fmaf(cf.y, xv.x, acc[1][0]);
            acc[1][1] = fmaf(cf.y, xv.y, acc[1][1]);
            acc[1][2] = fmaf(cf.y, xv.z, acc[1][2]);
            acc[1][3] = fmaf(cf.y, xv.w, acc[1][3]);
            acc[2][0] = fmaf(cf.z, xv.x, acc[2][0]);
            acc[2][1] = fmaf(cf.z, xv.y, acc[2][1]);
            acc[2][2] = fmaf(cf.z, xv.z, acc[2][2]);
            acc[2][3] = fmaf(cf.z, xv.w, acc[2][3]);
            acc[3][0] = fmaf(cf.w, xv.x, acc[3][0]);
            acc[3][1] = fmaf(cf.w, xv.y, acc[3][1]);
            acc[3][2] = fmaf(cf.w, xv.z, acc[3][2]);
            acc[3][3] = fmaf(cf.w, xv.w, acc[3][3]);
        }
        __syncwarp();
    }

    float inv[HH];
#pragma unroll
    for (int k = 0; k < HH; k++) inv[k] = 1.f / rs[k];
    float o[4] = {0.f, 0.f, 0.f, 0.f};
#pragma unroll
    for (int k = 0; k < HH; k++) {
        float4 w4 = ((const float4*)(W + k * FF))[lane];
        float v0 = acc[k][0] * w4.x * inv[k];
        float v1 = acc[k][1] * w4.y * inv[k];
        float v2 = acc[k][2] * w4.z * inv[k];
        float v3 = acc[k][3] * w4.w * inv[k];
        o[0] += v0 > 0.f ? v0 : expm1f(v0);
        o[1] += v1 > 0.f ? v1 : expm1f(v1);
        o[2] += v2 > 0.f ? v2 : expm1f(v2);
        o[3] += v3 > 0.f ? v3 : expm1f(v3);
    }
    float4 res = make_float4(o[0] * 0.25f, o[1] * 0.25f, o[2] * 0.25f, o[3] * 0.25f);
    ((float4*)(out + (size_t)node * FF))[lane] = res;
}

extern "C" void kernel_launch(void* const* d_in, const int* in_sizes, int n_in,
                              void* d_out, int out_size) {
    const float* x   = (const float*)d_in[0];   // [N, F]
    const int*   edge = (const int*)d_in[1];    // [2, E]
    const float* adj = (const float*)d_in[2];   // [E]
    const float* W   = (const float*)d_in[3];   // [H, F]
    const float* a   = (const float*)d_in[4];   // [H, 2F]
    float* out = (float*)d_out;

    int n = in_sizes[0] / FF;
    int e = in_sizes[2];
    const int* src = edge;
    const int* dst = edge + e;

    k_scores<<<1024, 256>>>(x, W, a, n);
    k_fill<<<(e + 255) / 256, 256>>>(src, dst, adj, e);
    k_agg<<<(n + 3) / 4, 128>>>(x, W, out, n);
}

// round 15
// speedup vs baseline: 1.3515x; 1.0647x over previous
#include <cuda_runtime.h>
#include <cstdint>

#define NN 100000
#define EE 1600000
#define FF 128
#define HH 4
#define LRELU_ALPHA 0.2f
#define CAP 64   // slots per node; degree ~ 1+Poisson(15), P(>64) ~ 1e-22

#define FULLM 0xFFFFFFFFu

// packed f32x2 fma: d = a*b + c lanewise on two packed fp32 (exact fp32 math)
#define FMA_F32X2(d, a, b, c) \
    asm("fma.rn.f32x2 %0, %1, %2, %3;" : "=l"(d) : "l"(a), "l"(b), "l"(c))
#define PACK_DUP(out, s) \
    asm("mov.b64 %0, {%1, %1};" : "=l"(out) : "f"(s))
#define UNPACK2(lo, hi, in) \
    asm("mov.b64 {%0, %1}, %2;" : "=f"(lo), "=f"(hi) : "l"(in))

struct __align__(8) Slot2 { int dst; float adj; };

// ---- device scratch (no allocations allowed) ----
__device__ float4 g_ssrc[NN];                // per-node src-scores, 4 heads
__device__ float4 g_sdst[NN];                // per-node dst-scores, 4 heads
__device__ int    g_cnt[NN];                 // per-node slot cursor / degree
__device__ Slot2  g_slot[(size_t)NN * CAP];  // slim per-src edge bins (51 MB)

// K1: grid-stride warp-per-node scores; weights register-cached per lane;
// software-pipelined next-row prefetch (MLP=2). Also zeroes g_cnt.
__global__ void k_scores(const float* __restrict__ x,
                         const float* __restrict__ W,
                         const float* __restrict__ a, int n) {
    int lane = threadIdx.x & 31;
    int gwarp = (blockIdx.x * blockDim.x + threadIdx.x) >> 5;
    int nwarps = (gridDim.x * blockDim.x) >> 5;

    // Per-lane weight cache: v=0..3 s-part head v, v=4..7 d-part head v-4.
    float4 wa[8];
#pragma unroll
    for (int v = 0; v < 8; v++) {
        int h = v & 3;
        float4 w4 = ((const float4*)(W + h * FF))[lane];
        float4 a4 = ((const float4*)(a + h * 2 * FF + ((v >= 4) ? FF : 0)))[lane];
        wa[v] = make_float4(w4.x * a4.x, w4.y * a4.y, w4.z * a4.z, w4.w * a4.w);
    }

    int node = gwarp;
    float4 xv = (node < n) ? ((const float4*)(x + (size_t)node * FF))[lane]
                           : make_float4(0.f, 0.f, 0.f, 0.f);
    for (; node < n; node += nwarps) {
        int nxt = node + nwarps;
        float4 xnext = (nxt < n) ? ((const float4*)(x + (size_t)nxt * FF))[lane]
                                 : xv;
        if (lane == 16) g_cnt[node] = 0;
        float p[8];
#pragma unroll
        for (int v = 0; v < 8; v++) {
            p[v] = xv.x * wa[v].x + xv.y * wa[v].y + xv.z * wa[v].z + xv.w * wa[v].w;
        }
        // multi-value halving reduction: 8 values -> lanes 0..7
#pragma unroll
        for (int s = 0; s < 3; s++) {
            int off = 1 << s;
            int half = 4 >> s;
            bool hi = (lane >> s) & 1;
#pragma unroll
            for (int i = 0; i < 4; i++) {
                if (i < half) {
                    float keep = hi ? p[i + half] : p[i];
                    float send = hi ? p[i] : p[i + half];
                    float recv = __shfl_xor_sync(FULLM, send, off);
                    p[i] = keep + recv;
                }
            }
        }
        float tot = p[0];
        tot += __shfl_xor_sync(FULLM, tot, 8);
        tot += __shfl_xor_sync(FULLM, tot, 16);
        if (lane < 8) {
            int v = ((lane & 1) << 2) | (lane & 2) | ((lane >> 2) & 1);  // bitrev3
            float* dst = (v < 4) ? ((float*)&g_ssrc[node]) + v
                                 : ((float*)&g_sdst[node]) + (v - 4);
            *dst = tot;
        }
        xv = xnext;
    }
}

// K2: slim binning only: per edge store {dst, adj} into src's bin (STG.64)
__global__ void k_fill(const int* __restrict__ src, const int* __restrict__ dst,
                       const float* __restrict__ adj, int e) {
    int i = blockIdx.x * blockDim.x + threadIdx.x;
    if (i >= e) return;
    int s = src[i];
    int idx = atomicAdd(&g_cnt[s], 1);
    Slot2 sl;
    sl.dst = dst[i];
    sl.adj = adj[i];
    g_slot[(size_t)s * CAP + idx] = sl;
}

// K3 (fused): warp per node. Per 32-edge chunk: lanes load slim slots,
// gather sdst, compute coefs lane-parallel, butterfly rowsum, stage coefs
// pre-packed as f32x2 dup-pairs; inner loop = 2 uniform LDS.128 + LDG.128
// + 8 packed FMAs per edge.
__global__ void k_agg(const float* __restrict__ x, const float* __restrict__ W,
                      float* __restrict__ out, int n) {
    __shared__ ulonglong2 s_pk[4][32][2];  // [warp][edge][{c0c0,c1c1},{c2c2,c3c3}]
    __shared__ int        s_dst[4][32];
    int lane = threadIdx.x & 31, warp = threadIdx.x >> 5;
    int node = blockIdx.x * (blockDim.x >> 5) + warp;
    if (node >= n) return;
    int cnt = g_cnt[node];
    size_t base = (size_t)node * CAP;
    float4 ssrc4 = g_ssrc[node];   // uniform broadcast load

    unsigned long long acc01[HH], acc23[HH];
#pragma unroll
    for (int k = 0; k < HH; k++) { acc01[k] = 0ULL; acc23[k] = 0ULL; }
    float rs[HH] = {0.f, 0.f, 0.f, 0.f};

    for (int b = 0; b < cnt; b += 32) {
        int m = cnt - b; if (m > 32) m = 32;
        int myd = 0;
        float myadj = 0.f;
        if (lane < m) {
            Slot2 sl = g_slot[base + b + lane];
            myd = sl.dst;
            myadj = sl.adj;
        }
        float4 sd4 = g_sdst[myd];  // random 16B gather (coef inputs)
        float z0 = ssrc4.x + sd4.x, z1 = ssrc4.y + sd4.y;
        float z2 = ssrc4.z + sd4.z, z3 = ssrc4.w + sd4.w;
        z0 = z0 > 0.f ? z0 : LRELU_ALPHA * z0;
        z1 = z1 > 0.f ? z1 : LRELU_ALPHA * z1;
        z2 = z2 > 0.f ? z2 : LRELU_ALPHA * z2;
        z3 = z3 > 0.f ? z3 : LRELU_ALPHA * z3;
        float c0 = __expf(z0) * myadj;   // lanes >= m: adj=0 -> coef 0
        float c1 = __expf(z1) * myadj;
        float c2 = __expf(z2) * myadj;
        float c3 = __expf(z3) * myadj;

        // rowsum: butterfly reduce of coefs
        float r0 = c0, r1 = c1, r2 = c2, r3 = c3;
#pragma unroll
        for (int o = 16; o > 0; o >>= 1) {
            r0 += __shfl_xor_sync(FULLM, r0, o);
            r1 += __shfl_xor_sync(FULLM, r1, o);
            r2 += __shfl_xor_sync(FULLM, r2, o);
            r3 += __shfl_xor_sync(FULLM, r3, o);
        }
        rs[0] += r0; rs[1] += r1; rs[2] += r2; rs[3] += r3;

        // stage dup-packed coef pairs (pack cost paid once per edge, not per lane-iter)
        ulonglong2 pa, pb;
        PACK_DUP(pa.x, c0); PACK_DUP(pa.y, c1);
        PACK_DUP(pb.x, c2); PACK_DUP(pb.y, c3);
        s_pk[warp][lane][0] = pa;
        s_pk[warp][lane][1] = pb;
        s_dst[warp][lane] = myd;
        __syncwarp();

        for (int j = 0; j < m; j++) {
            ulonglong2 p01 = s_pk[warp][j][0];
            ulonglong2 p23 = s_pk[warp][j][1];
            int d = s_dst[warp][j];
            ulonglong2 xv2 = ((const ulonglong2*)(x + (size_t)d * FF))[lane];
            FMA_F32X2(acc01[0], p01.x, xv2.x, acc01[0]);
            FMA_F32X2(acc23[0], p01.x, xv2.y, acc23[0]);
            FMA_F32X2(acc01[1], p01.y, xv2.x, acc01[1]);
            FMA_F32X2(acc23[1], p01.y, xv2.y, acc23[1]);
            FMA_F32X2(acc01[2], p23.x, xv2.x, acc01[2]);
            FMA_F32X2(acc23[2], p23.x, xv2.y, acc23[2]);
            FMA_F32X2(acc01[3], p23.y, xv2.x, acc01[3]);
            FMA_F32X2(acc23[3], p23.y, xv2.y, acc23[3]);
        }
        __syncwarp();
    }

    float inv[HH];
#pragma unroll
    for (int k = 0; k < HH; k++) inv[k] = 1.f / rs[k];
    float o[4] = {0.f, 0.f, 0.f, 0.f};
#pragma unroll
    for (int k = 0; k < HH; k++) {
        float a0, a1, a2, a3;
        UNPACK2(a0, a1, acc01[k]);
        UNPACK2(a2, a3, acc23[k]);
        float4 w4 = ((const float4*)(W + k * FF))[lane];
        float v0 = a0 * w4.x * inv[k];
        float v1 = a1 * w4.y * inv[k];
        float v2 = a2 * w4.z * inv[k];
        float v3 = a3 * w4.w * inv[k];
        o[0] += v0 > 0.f ? v0 : expm1f(v0);
        o[1] += v1 > 0.f ? v1 : expm1f(v1);
        o[2] += v2 > 0.f ? v2 : expm1f(v2);
        o[3] += v3 > 0.f ? v3 : expm1f(v3);
    }
    float4 res = make_float4(o[0] * 0.25f, o[1] * 0.25f, o[2] * 0.25f, o[3] * 0.25f);
    ((float4*)(out + (size_t)node * FF))[lane] = res;
}

extern "C" void kernel_launch(void* const* d_in, const int* in_sizes, int n_in,
                              void* d_out, int out_size) {
    const float* x   = (const float*)d_in[0];   // [N, F]
    const int*   edge = (const int*)d_in[1];    // [2, E]
    const float* adj = (const float*)d_in[2];   // [E]
    const float* W   = (const float*)d_in[3];   // [H, F]
    const float* a   = (const float*)d_in[4];   // [H, 2F]
    float* out = (float*)d_out;

    int n = in_sizes[0] / FF;
    int e = in_sizes[2];
    const int* src = edge;
    const int* dst = edge + e;

    k_scores<<<1024, 256>>>(x, W, a, n);
    k_fill<<<(e + 255) / 256, 256>>>(src, dst, adj, e);
    k_agg<<<(n + 3) / 4, 128>>>(x, W, out, n);
}

// round 17
// speedup vs baseline: 1.3626x; 1.0082x over previous
#include <cuda_runtime.h>
#include <cstdint>

#define NN 100000
#define EE 1600000
#define FF 128
#define HH 4
#define LRELU_ALPHA 0.2f
#define CAP 64   // slots per node; degree ~ 1+Poisson(15), P(>64) ~ 1e-22

#define FULLM 0xFFFFFFFFu

// packed f32x2 fma: d = a*b + c lanewise on two packed fp32 (exact fp32 math)
#define FMA_F32X2(d, a, b, c) \
    asm("fma.rn.f32x2 %0, %1, %2, %3;" : "=l"(d) : "l"(a), "l"(b), "l"(c))
#define PACK_DUP(out, s) \
    asm("mov.b64 %0, {%1, %1};" : "=l"(out) : "f"(s))
#define UNPACK2(lo, hi, in) \
    asm("mov.b64 {%0, %1}, %2;" : "=f"(lo), "=f"(hi) : "l"(in))

struct __align__(8) Slot2 { int dst; float adj; };

// ---- device scratch (no allocations allowed) ----
__device__ float4 g_ssrc[NN];                // per-node src-scores, 4 heads
__device__ float4 g_sdst[NN];                // per-node dst-scores, 4 heads
__device__ int    g_cnt[NN];                 // per-node slot cursor / degree
__device__ Slot2  g_slot[(size_t)NN * CAP];  // slim per-src edge bins (51 MB)

__global__ void k_zero(int n) {
    int i = blockIdx.x * blockDim.x + threadIdx.x;
    if (i < n) g_cnt[i] = 0;
}

// K1: grid-stride warp-per-node scores; weights register-cached per lane.
__global__ void k_scores(const float* __restrict__ x,
                         const float* __restrict__ W,
                         const float* __restrict__ a, int n) {
    int lane = threadIdx.x & 31;
    int gwarp = (blockIdx.x * blockDim.x + threadIdx.x) >> 5;
    int nwarps = (gridDim.x * blockDim.x) >> 5;

    // Per-lane weight cache: v=0..3 s-part head v, v=4..7 d-part head v-4.
    float4 wa[8];
#pragma unroll
    for (int v = 0; v < 8; v++) {
        int h = v & 3;
        float4 w4 = ((const float4*)(W + h * FF))[lane];
        float4 a4 = ((const float4*)(a + h * 2 * FF + ((v >= 4) ? FF : 0)))[lane];
        wa[v] = make_float4(w4.x * a4.x, w4.y * a4.y, w4.z * a4.z, w4.w * a4.w);
    }

    for (int node = gwarp; node < n; node += nwarps) {
        float4 xv = ((const float4*)(x + (size_t)node * FF))[lane];
        float p[8];
#pragma unroll
        for (int v = 0; v < 8; v++) {
            p[v] = xv.x * wa[v].x + xv.y * wa[v].y + xv.z * wa[v].z + xv.w * wa[v].w;
        }
        // multi-value halving reduction: 8 values -> lanes 0..7
#pragma unroll
        for (int s = 0; s < 3; s++) {
            int off = 1 << s;
            int half = 4 >> s;
            bool hi = (lane >> s) & 1;
#pragma unroll
            for (int i = 0; i < 4; i++) {
                if (i < half) {
                    float keep = hi ? p[i + half] : p[i];
                    float send = hi ? p[i] : p[i + half];
                    float recv = __shfl_xor_sync(FULLM, send, off);
                    p[i] = keep + recv;
                }
            }
        }
        float tot = p[0];
        tot += __shfl_xor_sync(FULLM, tot, 8);
        tot += __shfl_xor_sync(FULLM, tot, 16);
        if (lane < 8) {
            int v = ((lane & 1) << 2) | (lane & 2) | ((lane >> 2) & 1);  // bitrev3
            float* dst = (v < 4) ? ((float*)&g_ssrc[node]) + v
                                 : ((float*)&g_sdst[node]) + (v - 4);
            *dst = tot;
        }
    }
}

// K2: slim binning: 4 edges per thread, vectorized loads, scattered STG.64
__global__ void k_fill(const int* __restrict__ src, const int* __restrict__ dst,
                       const float* __restrict__ adj, int e) {
    int q = blockIdx.x * blockDim.x + threadIdx.x;
    int i0 = q * 4;
    if (i0 + 3 < e) {
        int4   s4 = ((const int4*)src)[q];
        int4   d4 = ((const int4*)dst)[q];
        float4 a4 = ((const float4*)adj)[q];
        int idx;
        Slot2 sl;
        idx = atomicAdd(&g_cnt[s4.x], 1); sl.dst = d4.x; sl.adj = a4.x;
        g_slot[(size_t)s4.x * CAP + idx] = sl;
        idx = atomicAdd(&g_cnt[s4.y], 1); sl.dst = d4.y; sl.adj = a4.y;
        g_slot[(size_t)s4.y * CAP + idx] = sl;
        idx = atomicAdd(&g_cnt[s4.z], 1); sl.dst = d4.z; sl.adj = a4.z;
        g_slot[(size_t)s4.z * CAP + idx] = sl;
        idx = atomicAdd(&g_cnt[s4.w], 1); sl.dst = d4.w; sl.adj = a4.w;
        g_slot[(size_t)s4.w * CAP + idx] = sl;
    } else {
        for (int i = i0; i < e; i++) {
            int s = src[i];
            int idx = atomicAdd(&g_cnt[s], 1);
            Slot2 sl; sl.dst = dst[i]; sl.adj = adj[i];
            g_slot[(size_t)s * CAP + idx] = sl;
        }
    }
}

// K3 (fused): warp per node; coef compute lane-parallel, staged dup-packed
// f32x2; rowsum deferred to one end-of-loop butterfly.
__global__ void k_agg(const float* __restrict__ x, const float* __restrict__ W,
                      float* __restrict__ out, int n) {
    __shared__ ulonglong2 s_pk[4][32][2];
    __shared__ int        s_dst[4][32];
    int lane = threadIdx.x & 31, warp = threadIdx.x >> 5;
    int node = blockIdx.x * (blockDim.x >> 5) + warp;
    if (node >= n) return;
    int cnt = g_cnt[node];
    size_t base = (size_t)node * CAP;
    float4 ssrc4 = g_ssrc[node];   // uniform broadcast load

    unsigned long long acc01[HH], acc23[HH];
#pragma unroll
    for (int k = 0; k < HH; k++) { acc01[k] = 0ULL; acc23[k] = 0ULL; }
    float rs0 = 0.f, rs1 = 0.f, rs2 = 0.f, rs3 = 0.f;   // per-lane, reduce later

    for (int b = 0; b < cnt; b += 32) {
        int m = cnt - b; if (m > 32) m = 32;
        int myd = 0;
        float myadj = 0.f;
        if (lane < m) {
            Slot2 sl = g_slot[base + b + lane];
            myd = sl.dst;
            myadj = sl.adj;
        }
        float4 sd4 = g_sdst[myd];
        float z0 = ssrc4.x + sd4.x, z1 = ssrc4.y + sd4.y;
        float z2 = ssrc4.z + sd4.z, z3 = ssrc4.w + sd4.w;
        z0 = z0 > 0.f ? z0 : LRELU_ALPHA * z0;
        z1 = z1 > 0.f ? z1 : LRELU_ALPHA * z1;
        z2 = z2 > 0.f ? z2 : LRELU_ALPHA * z2;
        z3 = z3 > 0.f ? z3 : LRELU_ALPHA * z3;
        float c0 = __expf(z0) * myadj;   // lanes >= m: adj=0 -> coef 0
        float c1 = __expf(z1) * myadj;
        float c2 = __expf(z2) * myadj;
        float c3 = __expf(z3) * myadj;
        rs0 += c0; rs1 += c1; rs2 += c2; rs3 += c3;

        ulonglong2 pa, pb;
        PACK_DUP(pa.x, c0); PACK_DUP(pa.y, c1);
        PACK_DUP(pb.x, c2); PACK_DUP(pb.y, c3);
        s_pk[warp][lane][0] = pa;
        s_pk[warp][lane][1] = pb;
        s_dst[warp][lane] = myd;
        __syncwarp();

        for (int j = 0; j < m; j++) {
            ulonglong2 p01 = s_pk[warp][j][0];
            ulonglong2 p23 = s_pk[warp][j][1];
            int d = s_dst[warp][j];
            ulonglong2 xv2 = ((const ulonglong2*)(x + (size_t)d * FF))[lane];
            FMA_F32X2(acc01[0], p01.x, xv2.x, acc01[0]);
            FMA_F32X2(acc23[0], p01.x, xv2.y, acc23[0]);
            FMA_F32X2(acc01[1], p01.y, xv2.x, acc01[1]);
            FMA_F32X2(acc23[1], p01.y, xv2.y, acc23[1]);
            FMA_F32X2(acc01[2], p23.x, xv2.x, acc01[2]);
            FMA_F32X2(acc23[2], p23.x, xv2.y, acc23[2]);
            FMA_F32X2(acc01[3], p23.y, xv2.x, acc01[3]);
            FMA_F32X2(acc23[3], p23.y, xv2.y, acc23[3]);
        }
        __syncwarp();
    }

    // single deferred rowsum butterfly
#pragma unroll
    for (int o = 16; o > 0; o >>= 1) {
        rs0 += __shfl_xor_sync(FULLM, rs0, o);
        rs1 += __shfl_xor_sync(FULLM, rs1, o);
        rs2 += __shfl_xor_sync(FULLM, rs2, o);
        rs3 += __shfl_xor_sync(FULLM, rs3, o);
    }
    float inv[HH];
    inv[0] = 1.f / rs0; inv[1] = 1.f / rs1;
    inv[2] = 1.f / rs2; inv[3] = 1.f / rs3;

    float o[4] = {0.f, 0.f, 0.f, 0.f};
#pragma unroll
    for (int k = 0; k < HH; k++) {
        float a0, a1, a2, a3;
        UNPACK2(a0, a1, acc01[k]);
        UNPACK2(a2, a3, acc23[k]);
        float4 w4 = ((const float4*)(W + k * FF))[lane];
        float v0 = a0 * w4.x * inv[k];
        float v1 = a1 * w4.y * inv[k];
        float v2 = a2 * w4.z * inv[k];
        float v3 = a3 * w4.w * inv[k];
        o[0] += v0 > 0.f ? v0 : expm1f(v0);
        o[1] += v1 > 0.f ? v1 : expm1f(v1);
        o[2] += v2 > 0.f ? v2 : expm1f(v2);
        o[3] += v3 > 0.f ? v3 : expm1f(v3);
    }
    float4 res = make_float4(o[0] * 0.25f, o[1] * 0.25f, o[2] * 0.25f, o[3] * 0.25f);
    ((float4*)(out + (size_t)node * FF))[lane] = res;
}

extern "C" void kernel_launch(void* const* d_in, const int* in_sizes, int n_in,
                              void* d_out, int out_size) {
    const float* x   = (const float*)d_in[0];   // [N, F]
    const int*   edge = (const int*)d_in[1];    // [2, E]
    const float* adj = (const float*)d_in[2];   // [E]
    const float* W   = (const float*)d_in[3];   // [H, F]
    const float* a   = (const float*)d_in[4];   // [H, 2F]
    float* out = (float*)d_out;

    int n = in_sizes[0] / FF;
    int e = in_sizes[2];
    const int* src = edge;
    const int* dst = edge + e;

    // one-time stream/event objects (resources, not device memory)
    static cudaStream_t s1 = nullptr;
    static cudaEvent_t ev_fork = nullptr, ev_join = nullptr;
    if (s1 == nullptr) {
        cudaStreamCreateWithFlags(&s1, cudaStreamNonBlocking);
        cudaEventCreateWithFlags(&ev_fork, cudaEventDisableTiming);
        cudaEventCreateWithFlags(&ev_join, cudaEventDisableTiming);
    }

    // fork: [k_zero -> k_fill] on s1 runs concurrently with k_scores on 0
    cudaEventRecord(ev_fork, 0);
    cudaStreamWaitEvent(s1, ev_fork, 0);
    k_zero<<<(n + 255) / 256, 256, 0, s1>>>(n);
    int eq = (e + 3) / 4;
    k_fill<<<(eq + 255) / 256, 256, 0, s1>>>(src, dst, adj, e);
    cudaEventRecord(ev_join, s1);

    k_scores<<<1024, 256>>>(x, W, a, n);

    // join, then aggregate
    cudaStreamWaitEvent(0, ev_join, 0);
    k_agg<<<(n + 3) / 4, 128>>>(x, W, out, n);
}